// round 1
// baseline (speedup 1.0000x reference)
#include <cuda_runtime.h>
#include <math.h>

// Problem constants
#define Bb 16
#define Tt 16
#define Cc 64
#define HD 64
#define HW 1024
#define IMW 32
#define NTHR 256
#define SROW 36
#define PLANE (34*SROW)   // 1224 floats per padded plane

// Scratch (device globals: no allocation allowed)
__device__ float g_h   [Bb*HD*HW];                    // 4 MB  hidden state
__device__ float g_hode[Bb*HD*HW];                    // 4 MB  h after ODE step
__device__ float g_rh  [Bb*HD*HW];                    // 4 MB  reset * h_ode
__device__ float g_u   [Bb*HD*HW];                    // 4 MB  update gate
__device__ float g_gx  [(size_t)Tt*Bb*2*HD*HW];       // 128 MB precomputed x-part of gates conv (+bias)
__device__ float g_cx  [(size_t)Tt*Bb*HD*HW];         // 64 MB  precomputed x-part of cand conv (+bias)

// ---------------------------------------------------------------------------
// Core: 3x3 SAME conv over 64 input channels for one 32x32 image, 8 output
// channels per CTA, 4 pixels per thread. Input plane double-buffered in smem
// with zeroed 1-px border (SAME padding). acc[px][oc] accumulated in regs.
// Dynamic smem: 8*576 weights + 2*PLANE planes = 28224 B.
// ---------------------------------------------------------------------------
__device__ __forceinline__ void conv_core64(
    const float* __restrict__ in,     // [64][1024]
    const float* __restrict__ wsrc,   // weight base; per-oc row stride = wstride9 floats; 576-float slice contiguous
    int wstride9, int ocb,
    float acc[4][8])
{
    extern __shared__ float smem[];
    float* ws = smem;                 // 4608 floats
    float* pl = smem + 8*576;         // 2*1224 floats
    const int tid = threadIdx.x;

    // Stage this CTA's 8 oc weight rows (64 ci x 9 taps each)
    for (int i = tid; i < 8*576; i += NTHR) {
        int oc = i / 576;
        ws[i] = wsrc[(size_t)(ocb*8 + oc)*wstride9 + (i - oc*576)];
    }
    // Zero both plane buffers (borders stay zero; interior overwritten per ci)
    for (int i = tid; i < 2*PLANE; i += NTHR) pl[i] = 0.f;

    const int row = tid >> 3;          // 0..31
    const int xb  = (tid & 7) << 2;    // 0,4,..,28

    float4 nxt = *reinterpret_cast<const float4*>(in + tid*4);
    __syncthreads();

    #pragma unroll 1
    for (int ci = 0; ci < 64; ci++) {
        float* cur = pl + (ci & 1)*PLANE;
        float* dst = cur + (row + 1)*SROW + xb + 1;
        dst[0] = nxt.x; dst[1] = nxt.y; dst[2] = nxt.z; dst[3] = nxt.w;
        __syncthreads();
        if (ci < 63) nxt = *reinterpret_cast<const float4*>(in + (ci+1)*HW + tid*4);

        // 3x6 input patch for this thread's 4 contiguous pixels
        float p[3][6];
        #pragma unroll
        for (int r = 0; r < 3; r++) {
            const float* s = cur + (row + r)*SROW + xb;
            float4 a  = *reinterpret_cast<const float4*>(s);
            float2 b2 = *reinterpret_cast<const float2*>(s + 4);
            p[r][0]=a.x; p[r][1]=a.y; p[r][2]=a.z; p[r][3]=a.w; p[r][4]=b2.x; p[r][5]=b2.y;
        }
        #pragma unroll
        for (int oc = 0; oc < 8; oc++) {
            const float* wp = ws + oc*576 + ci*9;
            float w0=wp[0],w1=wp[1],w2=wp[2],w3=wp[3],w4=wp[4],
                  w5=wp[5],w6=wp[6],w7=wp[7],w8=wp[8];
            #pragma unroll
            for (int px = 0; px < 4; px++) {
                acc[px][oc] += p[0][px]*w0 + p[0][px+1]*w1 + p[0][px+2]*w2
                             + p[1][px]*w3 + p[1][px+1]*w4 + p[1][px+2]*w5
                             + p[2][px]*w6 + p[2][px+1]*w7 + p[2][px+2]*w8;
            }
        }
    }
}

__device__ __forceinline__ float sigmoidf_(float x) { return 1.f / (1.f + expf(-x)); }

// ---------------------------------------------------------------------------
// Precompute x-contributions: out[t][b][co][pix] = conv(x_t, w_slice) + bias
// x_t = input[:, T-1-t].  grid = (cout/8, T*B)
// ---------------------------------------------------------------------------
__global__ void __launch_bounds__(NTHR) k_pre(
    const float* __restrict__ x0, const float* __restrict__ w, int wstride9,
    const float* __restrict__ bias, float* __restrict__ out, int cout)
{
    const int ocb = blockIdx.x, z = blockIdx.y;
    const int t = z >> 4, b = z & 15;
    const float* in = x0 + ((size_t)(b*Tt + (Tt-1-t))*Cc)*HW;

    float acc[4][8];
    #pragma unroll
    for (int oc = 0; oc < 8; oc++) {
        float bv = bias[ocb*8 + oc];
        #pragma unroll
        for (int px = 0; px < 4; px++) acc[px][oc] = bv;
    }
    conv_core64(in, w, wstride9, ocb, acc);

    const int row = threadIdx.x >> 3, xb = (threadIdx.x & 7) << 2;
    float* o = out + ((size_t)(t*Bb + b)*cout + ocb*8)*HW + row*IMW + xb;
    #pragma unroll
    for (int oc = 0; oc < 8; oc++)
        *reinterpret_cast<float4*>(o + oc*HW) =
            make_float4(acc[0][oc], acc[1][oc], acc[2][oc], acc[3][oc]);
}

// ---------------------------------------------------------------------------
// ODE step: h_ode = h + tanh(conv(h, w_ode) + b_ode) * dt   grid = (8, B)
// ---------------------------------------------------------------------------
__global__ void __launch_bounds__(NTHR) k_ode(
    const float* __restrict__ w, const float* __restrict__ bias,
    const float* __restrict__ ts, int step)
{
    const int ocb = blockIdx.x, b = blockIdx.y;
    const float* in = g_h + (size_t)b*HD*HW;

    float acc[4][8];
    #pragma unroll
    for (int oc = 0; oc < 8; oc++) {
        float bv = bias[ocb*8 + oc];
        #pragma unroll
        for (int px = 0; px < 4; px++) acc[px][oc] = bv;
    }
    conv_core64(in, w, 576, ocb, acc);

    const float dt = (step == 0) ? -0.01f : (ts[Tt-1-step] - ts[Tt-step]);
    const int row = threadIdx.x >> 3, xb = (threadIdx.x & 7) << 2;
    #pragma unroll
    for (int oc = 0; oc < 8; oc++) {
        size_t ib = ((size_t)b*HD + ocb*8 + oc)*HW + row*IMW + xb;
        float4 hv = *reinterpret_cast<const float4*>(&g_h[ib]);
        float4 r;
        r.x = hv.x + tanhf(acc[0][oc])*dt;
        r.y = hv.y + tanhf(acc[1][oc])*dt;
        r.z = hv.z + tanhf(acc[2][oc])*dt;
        r.w = hv.w + tanhf(acc[3][oc])*dt;
        *reinterpret_cast<float4*>(&g_hode[ib]) = r;
    }
}

// ---------------------------------------------------------------------------
// Gates: g = sigmoid(conv(h_ode, w_gates[:,64:]) + gx).  co<64 -> rh = g*h_ode
// co>=64 -> u = g.   grid = (16, B)
// ---------------------------------------------------------------------------
__global__ void __launch_bounds__(NTHR) k_gates(const float* __restrict__ w, int step)
{
    const int ocb = blockIdx.x, b = blockIdx.y;
    const float* in = g_hode + (size_t)b*HD*HW;

    float acc[4][8];
    #pragma unroll
    for (int px = 0; px < 4; px++)
        #pragma unroll
        for (int oc = 0; oc < 8; oc++) acc[px][oc] = 0.f;
    conv_core64(in, w, 1152, ocb, acc);

    const int row = threadIdx.x >> 3, xb = (threadIdx.x & 7) << 2;
    const int co0 = ocb*8;
    const float* pre = g_gx + ((size_t)(step*Bb + b)*(2*HD) + co0)*HW + row*IMW + xb;
    #pragma unroll
    for (int oc = 0; oc < 8; oc++) {
        float4 pv = *reinterpret_cast<const float4*>(pre + oc*HW);
        float4 g;
        g.x = sigmoidf_(acc[0][oc] + pv.x);
        g.y = sigmoidf_(acc[1][oc] + pv.y);
        g.z = sigmoidf_(acc[2][oc] + pv.z);
        g.w = sigmoidf_(acc[3][oc] + pv.w);
        if (co0 < HD) {  // reset half: write r * h_ode
            size_t ib = ((size_t)b*HD + co0 + oc)*HW + row*IMW + xb;
            float4 hv = *reinterpret_cast<const float4*>(&g_hode[ib]);
            g.x *= hv.x; g.y *= hv.y; g.z *= hv.z; g.w *= hv.w;
            *reinterpret_cast<float4*>(&g_rh[ib]) = g;
        } else {         // update half
            size_t ib = ((size_t)b*HD + co0 - HD + oc)*HW + row*IMW + xb;
            *reinterpret_cast<float4*>(&g_u[ib]) = g;
        }
    }
}

// ---------------------------------------------------------------------------
// Candidate + GRU update + mask:
//   c = tanh(conv(rh, w_can[:,64:]) + cx);  h = h_ode + m*u*(c - h_ode)
// grid = (8, B)
// ---------------------------------------------------------------------------
__global__ void __launch_bounds__(NTHR) k_cand(
    const float* __restrict__ w, const float* __restrict__ mask, int step)
{
    const int ocb = blockIdx.x, b = blockIdx.y;
    const float* in = g_rh + (size_t)b*HD*HW;

    float acc[4][8];
    #pragma unroll
    for (int px = 0; px < 4; px++)
        #pragma unroll
        for (int oc = 0; oc < 8; oc++) acc[px][oc] = 0.f;
    conv_core64(in, w, 1152, ocb, acc);

    const float m = mask[b*Tt + (Tt-1-step)];
    const int row = threadIdx.x >> 3, xb = (threadIdx.x & 7) << 2;
    const float* pre = g_cx + ((size_t)(step*Bb + b)*HD + ocb*8)*HW + row*IMW + xb;
    #pragma unroll
    for (int oc = 0; oc < 8; oc++) {
        size_t ib = ((size_t)b*HD + ocb*8 + oc)*HW + row*IMW + xb;
        float4 pv = *reinterpret_cast<const float4*>(pre + oc*HW);
        float4 ho = *reinterpret_cast<const float4*>(&g_hode[ib]);
        float4 uu = *reinterpret_cast<const float4*>(&g_u[ib]);
        float4 r;
        r.x = ho.x + m*uu.x*(tanhf(acc[0][oc] + pv.x) - ho.x);
        r.y = ho.y + m*uu.y*(tanhf(acc[1][oc] + pv.y) - ho.y);
        r.z = ho.z + m*uu.z*(tanhf(acc[2][oc] + pv.z) - ho.z);
        r.w = ho.w + m*uu.w*(tanhf(acc[3][oc] + pv.w) - ho.w);
        *reinterpret_cast<float4*>(&g_h[ib]) = r;
    }
}

// ---------------------------------------------------------------------------
// Head: z1 = relu(W1 h + b1); z2 = W2 z1 + b2; out = [z2[:64] ; |z2[64:]|]
// grid = (4, B), 256 pixels per CTA, one pixel per thread.
// Dynamic smem: w1 (4096) + w2 (8192) floats = 48 KB.
// ---------------------------------------------------------------------------
__global__ void __launch_bounds__(NTHR) k_final(
    const float* __restrict__ w1, const float* __restrict__ b1,
    const float* __restrict__ w2, const float* __restrict__ b2,
    float* __restrict__ out)
{
    extern __shared__ float smem[];
    float* w1s = smem;          // [64][64]
    float* w2s = smem + 4096;   // [128][64]
    const int tid = threadIdx.x, pb = blockIdx.x, b = blockIdx.y;
    for (int i = tid; i < 4096; i += NTHR) w1s[i] = w1[i];
    for (int i = tid; i < 8192; i += NTHR) w2s[i] = w2[i];
    __syncthreads();

    const int pix = pb*NTHR + tid;
    float z1[64];
    #pragma unroll
    for (int co = 0; co < 64; co++) z1[co] = b1[co];
    for (int ci = 0; ci < 64; ci++) {
        float hv = g_h[((size_t)b*HD + ci)*HW + pix];
        #pragma unroll
        for (int co = 0; co < 64; co++) z1[co] += w1s[co*64 + ci]*hv;
    }
    #pragma unroll
    for (int co = 0; co < 64; co++) z1[co] = fmaxf(z1[co], 0.f);

    for (int co2 = 0; co2 < 128; co2++) {
        float a = b2[co2];
        #pragma unroll
        for (int ci = 0; ci < 64; ci++) a += w2s[co2*64 + ci]*z1[ci];
        if (co2 < 64)
            out[((size_t)b*HD + co2)*HW + pix] = a;
        else
            out[(size_t)Bb*HD*HW + ((size_t)b*HD + (co2 - 64))*HW + pix] = fabsf(a);
    }
}

// ---------------------------------------------------------------------------
extern "C" void kernel_launch(void* const* d_in, const int* in_sizes, int n_in,
                              void* d_out, int out_size)
{
    const float* input   = (const float*)d_in[0];
    const float* ts      = (const float*)d_in[1];
    const float* mask    = (const float*)d_in[2];
    const float* w_gates = (const float*)d_in[3];
    const float* b_gates = (const float*)d_in[4];
    const float* w_can   = (const float*)d_in[5];
    const float* b_can   = (const float*)d_in[6];
    const float* w_ode   = (const float*)d_in[7];
    const float* b_ode   = (const float*)d_in[8];
    const float* w_t1    = (const float*)d_in[9];
    const float* b_t1    = (const float*)d_in[10];
    const float* w_t2    = (const float*)d_in[11];
    const float* b_t2    = (const float*)d_in[12];
    float* out = (float*)d_out;

    float *hptr, *gxp, *cxp;
    cudaGetSymbolAddress((void**)&hptr, g_h);
    cudaGetSymbolAddress((void**)&gxp,  g_gx);
    cudaGetSymbolAddress((void**)&cxp,  g_cx);

    cudaMemsetAsync(hptr, 0, (size_t)Bb*HD*HW*sizeof(float));

    const int CSM = (8*576 + 2*PLANE) * (int)sizeof(float);  // 28224 B

    // Precompute x-contributions for all T steps (x-halves of gates/cand convs)
    k_pre<<<dim3(16, Tt*Bb), NTHR, CSM>>>(input, w_gates, 1152, b_gates, gxp, 2*HD);
    k_pre<<<dim3(8,  Tt*Bb), NTHR, CSM>>>(input, w_can,   1152, b_can,   cxp, HD);

    // Sequential scan (reversed time handled inside via step index)
    for (int s = 0; s < Tt; s++) {
        k_ode  <<<dim3(8,  Bb), NTHR, CSM>>>(w_ode, b_ode, ts, s);
        k_gates<<<dim3(16, Bb), NTHR, CSM>>>(w_gates + 64*9, s);
        k_cand <<<dim3(8,  Bb), NTHR, CSM>>>(w_can   + 64*9, mask, s);
    }

    // Head
    k_final<<<dim3(4, Bb), NTHR, 12288*(int)sizeof(float)>>>(w_t1, b_t1, w_t2, b_t2, out);
}

// round 2
// speedup vs baseline: 1.2044x; 1.2044x over previous
#include <cuda_runtime.h>
#include <math.h>

// Problem constants
#define Bb 16
#define Tt 16
#define Cc 64
#define HD 64
#define HW 1024
#define IMW 32
#define NT 128
#define SROW 36
#define PLANE (34*SROW)   // 1224 floats per padded plane

// Scratch (device globals: no allocation allowed)
__device__ float g_h   [Bb*HD*HW];
__device__ float g_hode[Bb*HD*HW];
__device__ float g_rh  [Bb*HD*HW];
__device__ float g_u   [Bb*HD*HW];
__device__ float g_gx  [(size_t)Tt*Bb*2*HD*HW];   // x-part of gates conv (+bias)
__device__ float g_cx  [(size_t)Tt*Bb*HD*HW];     // x-part of cand conv (+bias)

// ---------------------------------------------------------------------------
// Core: 3x3 SAME conv over 64 input channels, one 32x32 image, 4 output
// channels per CTA, 8 pixels per thread (128 threads). Two input channels
// processed per barrier; 4 smem planes (paired double buffer) with zeroed
// 1-px borders. Dynamic smem: 4*576 weights + 4*PLANE = 28800 B.
// ---------------------------------------------------------------------------
__device__ __forceinline__ void conv_core64(
    const float* __restrict__ in,     // [64][1024]
    const float* __restrict__ wsrc,   // per-oc row stride = wstride9 floats
    int wstride9, int ocb,
    float acc[4][8])
{
    extern __shared__ float smem[];
    float* ws = smem;                 // 2304 floats
    float* pl = smem + 4*576;         // 4*1224 floats
    const int tid = threadIdx.x;
    const int row = tid >> 2;          // 0..31
    const int xb  = (tid & 3) << 3;    // 0,8,16,24

    for (int i = tid; i < 4*576; i += NT) {
        int oc = i / 576;
        ws[i] = wsrc[(size_t)(ocb*4 + oc)*wstride9 + (i - oc*576)];
    }
    for (int i = tid; i < 4*PLANE; i += NT) pl[i] = 0.f;

    const int goff = row*IMW + xb;
    float4 n0a = *reinterpret_cast<const float4*>(in + goff);
    float4 n0b = *reinterpret_cast<const float4*>(in + goff + 4);
    float4 n1a = *reinterpret_cast<const float4*>(in + HW + goff);
    float4 n1b = *reinterpret_cast<const float4*>(in + HW + goff + 4);
    __syncthreads();   // zero/weights visible before interior stores

    #pragma unroll 1
    for (int pr = 0; pr < 32; pr++) {
        float* b0 = pl + (pr & 1)*2*PLANE;
        float* b1 = b0 + PLANE;
        {
            float* d0 = b0 + (row + 1)*SROW + xb + 1;
            d0[0]=n0a.x; d0[1]=n0a.y; d0[2]=n0a.z; d0[3]=n0a.w;
            d0[4]=n0b.x; d0[5]=n0b.y; d0[6]=n0b.z; d0[7]=n0b.w;
            float* d1 = b1 + (row + 1)*SROW + xb + 1;
            d1[0]=n1a.x; d1[1]=n1a.y; d1[2]=n1a.z; d1[3]=n1a.w;
            d1[4]=n1b.x; d1[5]=n1b.y; d1[6]=n1b.z; d1[7]=n1b.w;
        }
        __syncthreads();
        if (pr < 31) {
            const float* g = in + (2*pr + 2)*HW + goff;
            n0a = *reinterpret_cast<const float4*>(g);
            n0b = *reinterpret_cast<const float4*>(g + 4);
            n1a = *reinterpret_cast<const float4*>(g + HW);
            n1b = *reinterpret_cast<const float4*>(g + HW + 4);
        }
        #pragma unroll
        for (int half = 0; half < 2; half++) {
            const float* cur = half ? b1 : b0;
            const int ci = 2*pr + half;
            float p[3][10];
            #pragma unroll
            for (int r = 0; r < 3; r++) {
                const float* s = cur + (row + r)*SROW + xb;   // 16B aligned
                float4 a = *reinterpret_cast<const float4*>(s);
                float4 b = *reinterpret_cast<const float4*>(s + 4);
                float2 c = *reinterpret_cast<const float2*>(s + 8);
                p[r][0]=a.x; p[r][1]=a.y; p[r][2]=a.z; p[r][3]=a.w;
                p[r][4]=b.x; p[r][5]=b.y; p[r][6]=b.z; p[r][7]=b.w;
                p[r][8]=c.x; p[r][9]=c.y;
            }
            #pragma unroll
            for (int oc = 0; oc < 4; oc++) {
                const float* wp = ws + oc*576 + ci*9;
                float w0=wp[0],w1=wp[1],w2=wp[2],w3=wp[3],w4=wp[4],
                      w5=wp[5],w6=wp[6],w7=wp[7],w8=wp[8];
                #pragma unroll
                for (int px = 0; px < 8; px++) {
                    acc[oc][px] += p[0][px]*w0 + p[0][px+1]*w1 + p[0][px+2]*w2
                                 + p[1][px]*w3 + p[1][px+1]*w4 + p[1][px+2]*w5
                                 + p[2][px]*w6 + p[2][px+1]*w7 + p[2][px+2]*w8;
                }
            }
        }
    }
}

__device__ __forceinline__ float sigmoidf_(float x) { return 1.f / (1.f + expf(-x)); }

__device__ __forceinline__ void st8(float* o, const float acc[8]) {
    *reinterpret_cast<float4*>(o)     = make_float4(acc[0],acc[1],acc[2],acc[3]);
    *reinterpret_cast<float4*>(o + 4) = make_float4(acc[4],acc[5],acc[6],acc[7]);
}

// ---------------------------------------------------------------------------
// Precompute x-contributions: out[t][b][co][pix] = conv(x_{T-1-t}) + bias
// grid = (cout/4, T*B)
// ---------------------------------------------------------------------------
__global__ void __launch_bounds__(NT) k_pre(
    const float* __restrict__ x0, const float* __restrict__ w, int wstride9,
    const float* __restrict__ bias, float* __restrict__ out, int cout)
{
    const int ocb = blockIdx.x, z = blockIdx.y;
    const int t = z >> 4, b = z & 15;
    const float* in = x0 + ((size_t)(b*Tt + (Tt-1-t))*Cc)*HW;

    float acc[4][8];
    #pragma unroll
    for (int oc = 0; oc < 4; oc++) {
        float bv = bias[ocb*4 + oc];
        #pragma unroll
        for (int px = 0; px < 8; px++) acc[oc][px] = bv;
    }
    conv_core64(in, w, wstride9, ocb, acc);

    const int row = threadIdx.x >> 2, xb = (threadIdx.x & 3) << 3;
    float* o = out + ((size_t)(t*Bb + b)*cout + ocb*4)*HW + row*IMW + xb;
    #pragma unroll
    for (int oc = 0; oc < 4; oc++) st8(o + oc*HW, acc[oc]);
}

// ---------------------------------------------------------------------------
// ODE: h_ode = h + tanh(conv(h)+b)*dt   grid = (16, B)
// ---------------------------------------------------------------------------
__global__ void __launch_bounds__(NT) k_ode(
    const float* __restrict__ w, const float* __restrict__ bias,
    const float* __restrict__ ts, int step)
{
    const int ocb = blockIdx.x, b = blockIdx.y;
    const float* in = g_h + (size_t)b*HD*HW;

    float acc[4][8];
    #pragma unroll
    for (int oc = 0; oc < 4; oc++) {
        float bv = bias[ocb*4 + oc];
        #pragma unroll
        for (int px = 0; px < 8; px++) acc[oc][px] = bv;
    }
    conv_core64(in, w, 576, ocb, acc);

    const float dt = (step == 0) ? -0.01f : (ts[Tt-1-step] - ts[Tt-step]);
    const int row = threadIdx.x >> 2, xb = (threadIdx.x & 3) << 3;
    #pragma unroll
    for (int oc = 0; oc < 4; oc++) {
        size_t ib = ((size_t)b*HD + ocb*4 + oc)*HW + row*IMW + xb;
        float r[8];
        #pragma unroll
        for (int px = 0; px < 8; px++)
            r[px] = g_h[ib + px] + tanhf(acc[oc][px])*dt;
        st8(&g_hode[ib], r);
    }
}

// ---------------------------------------------------------------------------
// Gates: g = sigmoid(conv(h_ode)+gx).  co<64 -> rh = g*h_ode; else u = g.
// grid = (32, B)
// ---------------------------------------------------------------------------
__global__ void __launch_bounds__(NT) k_gates(const float* __restrict__ w, int step)
{
    const int ocb = blockIdx.x, b = blockIdx.y;
    const float* in = g_hode + (size_t)b*HD*HW;

    float acc[4][8];
    #pragma unroll
    for (int oc = 0; oc < 4; oc++)
        #pragma unroll
        for (int px = 0; px < 8; px++) acc[oc][px] = 0.f;
    conv_core64(in, w, 1152, ocb, acc);

    const int row = threadIdx.x >> 2, xb = (threadIdx.x & 3) << 3;
    const int co0 = ocb*4;
    const float* pre = g_gx + ((size_t)(step*Bb + b)*(2*HD) + co0)*HW + row*IMW + xb;
    #pragma unroll
    for (int oc = 0; oc < 4; oc++) {
        float g[8];
        #pragma unroll
        for (int px = 0; px < 8; px++)
            g[px] = sigmoidf_(acc[oc][px] + pre[oc*HW + px]);
        if (co0 < HD) {
            size_t ib = ((size_t)b*HD + co0 + oc)*HW + row*IMW + xb;
            #pragma unroll
            for (int px = 0; px < 8; px++) g[px] *= g_hode[ib + px];
            st8(&g_rh[ib], g);
        } else {
            size_t ib = ((size_t)b*HD + co0 - HD + oc)*HW + row*IMW + xb;
            st8(&g_u[ib], g);
        }
    }
}

// ---------------------------------------------------------------------------
// Candidate + GRU update + mask. grid = (16, B)
// ---------------------------------------------------------------------------
__global__ void __launch_bounds__(NT) k_cand(
    const float* __restrict__ w, const float* __restrict__ mask, int step)
{
    const int ocb = blockIdx.x, b = blockIdx.y;
    const float* in = g_rh + (size_t)b*HD*HW;

    float acc[4][8];
    #pragma unroll
    for (int oc = 0; oc < 4; oc++)
        #pragma unroll
        for (int px = 0; px < 8; px++) acc[oc][px] = 0.f;
    conv_core64(in, w, 1152, ocb, acc);

    const float m = mask[b*Tt + (Tt-1-step)];
    const int row = threadIdx.x >> 2, xb = (threadIdx.x & 3) << 3;
    const float* pre = g_cx + ((size_t)(step*Bb + b)*HD + ocb*4)*HW + row*IMW + xb;
    #pragma unroll
    for (int oc = 0; oc < 4; oc++) {
        size_t ib = ((size_t)b*HD + ocb*4 + oc)*HW + row*IMW + xb;
        float r[8];
        #pragma unroll
        for (int px = 0; px < 8; px++) {
            float ho = g_hode[ib + px];
            float c  = tanhf(acc[oc][px] + pre[oc*HW + px]);
            r[px] = ho + m*g_u[ib + px]*(c - ho);
        }
        st8(&g_h[ib], r);
    }
}

// ---------------------------------------------------------------------------
// Head: z1 = relu(W1 h + b1); z2 = W2 z1 + b2; out = [z2[:64] ; |z2[64:]|]
// grid = (4, B)
// ---------------------------------------------------------------------------
__global__ void __launch_bounds__(256) k_final(
    const float* __restrict__ w1, const float* __restrict__ b1,
    const float* __restrict__ w2, const float* __restrict__ b2,
    float* __restrict__ out)
{
    extern __shared__ float smem[];
    float* w1s = smem;          // [64][64]
    float* w2s = smem + 4096;   // [128][64]
    const int tid = threadIdx.x, pb = blockIdx.x, b = blockIdx.y;
    for (int i = tid; i < 4096; i += 256) w1s[i] = w1[i];
    for (int i = tid; i < 8192; i += 256) w2s[i] = w2[i];
    __syncthreads();

    const int pix = pb*256 + tid;
    float z1[64];
    #pragma unroll
    for (int co = 0; co < 64; co++) z1[co] = b1[co];
    for (int ci = 0; ci < 64; ci++) {
        float hv = g_h[((size_t)b*HD + ci)*HW + pix];
        #pragma unroll
        for (int co = 0; co < 64; co++) z1[co] += w1s[co*64 + ci]*hv;
    }
    #pragma unroll
    for (int co = 0; co < 64; co++) z1[co] = fmaxf(z1[co], 0.f);

    for (int co2 = 0; co2 < 128; co2++) {
        float a = b2[co2];
        #pragma unroll
        for (int ci = 0; ci < 64; ci++) a += w2s[co2*64 + ci]*z1[ci];
        if (co2 < 64)
            out[((size_t)b*HD + co2)*HW + pix] = a;
        else
            out[(size_t)Bb*HD*HW + ((size_t)b*HD + (co2 - 64))*HW + pix] = fabsf(a);
    }
}

// ---------------------------------------------------------------------------
extern "C" void kernel_launch(void* const* d_in, const int* in_sizes, int n_in,
                              void* d_out, int out_size)
{
    const float* input   = (const float*)d_in[0];
    const float* ts      = (const float*)d_in[1];
    const float* mask    = (const float*)d_in[2];
    const float* w_gates = (const float*)d_in[3];
    const float* b_gates = (const float*)d_in[4];
    const float* w_can   = (const float*)d_in[5];
    const float* b_can   = (const float*)d_in[6];
    const float* w_ode   = (const float*)d_in[7];
    const float* b_ode   = (const float*)d_in[8];
    const float* w_t1    = (const float*)d_in[9];
    const float* b_t1    = (const float*)d_in[10];
    const float* w_t2    = (const float*)d_in[11];
    const float* b_t2    = (const float*)d_in[12];
    float* out = (float*)d_out;

    float *hptr, *gxp, *cxp;
    cudaGetSymbolAddress((void**)&hptr, g_h);
    cudaGetSymbolAddress((void**)&gxp,  g_gx);
    cudaGetSymbolAddress((void**)&cxp,  g_cx);

    cudaMemsetAsync(hptr, 0, (size_t)Bb*HD*HW*sizeof(float));

    const int CSM = (4*576 + 4*PLANE) * (int)sizeof(float);  // 28800 B

    k_pre<<<dim3(32, Tt*Bb), NT, CSM>>>(input, w_gates, 1152, b_gates, gxp, 2*HD);
    k_pre<<<dim3(16, Tt*Bb), NT, CSM>>>(input, w_can,   1152, b_can,   cxp, HD);

    for (int s = 0; s < Tt; s++) {
        k_ode  <<<dim3(16, Bb), NT, CSM>>>(w_ode, b_ode, ts, s);
        k_gates<<<dim3(32, Bb), NT, CSM>>>(w_gates + 64*9, s);
        k_cand <<<dim3(16, Bb), NT, CSM>>>(w_can   + 64*9, mask, s);
    }

    k_final<<<dim3(4, Bb), 256, 12288*(int)sizeof(float)>>>(w_t1, b_t1, w_t2, b_t2, out);
}